// round 6
// baseline (speedup 1.0000x reference)
#include <cuda_runtime.h>

#define IH 4096
#define IW 4096
#define OH 4082
#define OW 4082

#define TILE_R 64          // output rows per block
#define TILE_C 96          // output cols per block (6 warps x 16)
#define NWARP  6
#define NTHR   192
#define IN_R   78          // TILE_R + 14 input rows staged
#define PITCH_F 128        // smem row pitch in floats (32 x 16B chunks, swizzle headroom)
#define PITCH_B 512
#define LOAD_F4 28         // float4 per staged row (112 floats >= 110 needed)

typedef unsigned long long ull;

__device__ __forceinline__ ull fma2(ull a, ull b, ull c) {
    ull d;
    asm("fma.rn.f32x2 %0, %1, %2, %3;" : "=l"(d) : "l"(a), "l"(b), "l"(c));
    return d;
}
__device__ __forceinline__ ull add2(ull a, ull b) {
    ull d;
    asm("add.rn.f32x2 %0, %1, %2;" : "=l"(d) : "l"(a), "l"(b));
    return d;
}
__device__ __forceinline__ ull mkpair(unsigned lo, unsigned hi) {
    ull d;
    asm("mov.b64 %0, {%1, %2};" : "=l"(d) : "r"(lo), "r"(hi));
    return d;
}

// One weight row (15 taps) applied to one output row's 8 f32x2 accumulators.
// a[q] = (f[2q], f[2q+1])  q=0..14 ; b[q] = (f[2q+1], f[2q+2]) q=0..13
// kx=2m   -> pair a[p+m]
// kx=2m+1 -> pair b[p+m]
__device__ __forceinline__ void conv_row(ull* acc, const ull* a, const ull* b,
                                         const ull* __restrict__ wr) {
#pragma unroll
    for (int m = 0; m < 8; ++m) {
        ull w = wr[2 * m];
#pragma unroll
        for (int p = 0; p < 8; ++p) acc[p] = fma2(a[p + m], w, acc[p]);
    }
#pragma unroll
    for (int m = 0; m < 7; ++m) {
        ull w = wr[2 * m + 1];
#pragma unroll
        for (int p = 0; p < 8; ++p) acc[p] = fma2(b[p + m], w, acc[p]);
    }
}

// Load the 30-float window (as 15 aligned pairs) for input row ir, build the
// 14 odd-shift pairs in registers.
__device__ __forceinline__ void load_win(const float* sA, int ir, int c0,
                                         ull* a, ull* b) {
    const unsigned xv = (((unsigned)ir) >> 1) & 7u;
    const char* rowp = reinterpret_cast<const char*>(sA) + ir * PITCH_B;
#pragma unroll
    for (int i = 0; i < 7; ++i) {
        ulonglong2 t = *reinterpret_cast<const ulonglong2*>(
            rowp + ((unsigned)((c0 + i) ^ xv) << 4));
        a[2 * i] = t.x;
        a[2 * i + 1] = t.y;
    }
    a[14] = *reinterpret_cast<const ull*>(rowp + ((unsigned)((c0 + 7) ^ xv) << 4));
#pragma unroll
    for (int q = 0; q < 14; ++q)
        b[q] = mkpair((unsigned)(a[q] >> 32), (unsigned)(a[q + 1] & 0xffffffffULL));
}

__global__ void __launch_bounds__(NTHR, 2)
conv15_kernel(const float* __restrict__ X, const float* __restrict__ Wt,
              const float* __restrict__ bias, float* __restrict__ out) {
    __shared__ float sA[IN_R * PITCH_F];
    __shared__ ull sW[225];

    const int tid = threadIdx.x;
    const int gro = blockIdx.y * TILE_R;
    const int gco = blockIdx.x * TILE_C;

    // Stage weights as duplicated f32x2 pairs. (grid-stride: 225 > NTHR!)
    for (int i = tid; i < 225; i += NTHR) {
        float w = Wt[i];
        unsigned wb = __float_as_uint(w);
        sW[i] = mkpair(wb, wb);
    }

    // Stage the input tile with 16B-granularity XOR swizzle: chunk ^ ((row>>1)&7).
    for (int idx = tid; idx < IN_R * LOAD_F4; idx += NTHR) {
        int r = idx / LOAD_F4;
        int c4 = idx - r * LOAD_F4;
        int gr = gro + r;
        int gc = gco + c4 * 4;
        float4 v = make_float4(0.f, 0.f, 0.f, 0.f);
        if (gr < IH && gc < IW)
            v = *reinterpret_cast<const float4*>(X + (size_t)gr * IW + gc);
        unsigned xv = (((unsigned)r) >> 1) & 7u;
        *reinterpret_cast<float4*>(sA + r * PITCH_F + (((unsigned)c4 ^ xv) << 2)) = v;
    }
    __syncthreads();

    const int warp = tid >> 5;         // 0..5 -> 16-col strip
    const int lane = tid & 31;
    const int c0 = warp * 4;           // window base in 16B chunks (floats warp*16)
    const int r0 = lane * 2;           // two output rows per lane

    ull acc0[8], acc1[8];
#pragma unroll
    for (int p = 0; p < 8; ++p) { acc0[p] = 0ULL; acc1[p] = 0ULL; }

    ull a[15], b[14];

    // j = 0 : only row0 (ky = 0)
    load_win(sA, r0, c0, a, b);
    conv_row(acc0, a, b, sW);

    // j = 1..14 : row0 (ky=j) and row1 (ky=j-1)
#pragma unroll 1
    for (int j = 1; j <= 14; ++j) {
        load_win(sA, r0 + j, c0, a, b);
        conv_row(acc0, a, b, sW + j * 15);
        conv_row(acc1, a, b, sW + (j - 1) * 15);
    }

    // j = 15 : only row1 (ky = 14)
    load_win(sA, r0 + 15, c0, a, b);
    conv_row(acc1, a, b, sW + 14 * 15);

    // Epilogue: add bias, store as aligned 8B pairs (OW even -> pairs all-in/all-out).
    const float bv = bias[0];
    const unsigned bb = __float_as_uint(bv);
    const ull bpair = mkpair(bb, bb);
    const int oc0 = gco + warp * 16;

    {
        int orow = gro + r0;
        if (orow < OH) {
            float* op = out + (size_t)orow * OW;
#pragma unroll
            for (int p = 0; p < 8; ++p) {
                int oc = oc0 + 2 * p;
                if (oc < OW)
                    *reinterpret_cast<ull*>(op + oc) = add2(acc0[p], bpair);
            }
        }
    }
    {
        int orow = gro + r0 + 1;
        if (orow < OH) {
            float* op = out + (size_t)orow * OW;
#pragma unroll
            for (int p = 0; p < 8; ++p) {
                int oc = oc0 + 2 * p;
                if (oc < OW)
                    *reinterpret_cast<ull*>(op + oc) = add2(acc1[p], bpair);
            }
        }
    }
}

extern "C" void kernel_launch(void* const* d_in, const int* in_sizes, int n_in,
                              void* d_out, int out_size) {
    (void)in_sizes; (void)n_in; (void)out_size;
    const float* X = (const float*)d_in[0];
    const float* W = (const float*)d_in[1];
    const float* b = (const float*)d_in[2];
    float* out = (float*)d_out;

    dim3 grid((OW + TILE_C - 1) / TILE_C, (OH + TILE_R - 1) / TILE_R);
    conv15_kernel<<<grid, NTHR>>>(X, W, b, out);
}

// round 8
// speedup vs baseline: 1.0689x; 1.0689x over previous
#include <cuda_runtime.h>

#define IH 4096
#define IW 4096
#define OH 4082
#define OW 4082

#define TILE_R 32          // output rows per block (1 row per lane)
#define TILE_C 96          // output cols per block (6 warps x 16)
#define NTHR   192
#define IN_R   46          // TILE_R + 14 input rows staged
#define PITCH_F 128        // smem row pitch in floats (32 x 16B chunks)
#define PITCH_B 512
#define LOAD_F4 28         // float4 per staged row (112 floats >= 110 needed)

typedef unsigned long long ull;

__device__ __forceinline__ ull fma2(ull a, ull b, ull c) {
    ull d;
    asm("fma.rn.f32x2 %0, %1, %2, %3;" : "=l"(d) : "l"(a), "l"(b), "l"(c));
    return d;
}
__device__ __forceinline__ ull add2(ull a, ull b) {
    ull d;
    asm("add.rn.f32x2 %0, %1, %2;" : "=l"(d) : "l"(a), "l"(b));
    return d;
}
__device__ __forceinline__ ull mkpair(unsigned lo, unsigned hi) {
    ull d;
    asm("mov.b64 %0, {%1, %2};" : "=l"(d) : "r"(lo), "r"(hi));
    return d;
}

// One weight row (15 taps, stored as 8 aligned ull-pairs) applied to 8 f32x2 accs.
// a[q] = (f[2q], f[2q+1])  q=0..14 ; b[q] = (f[2q+1], f[2q+2]) q=0..13
// kx=2m -> pair a[p+m] with w2[m].x ; kx=2m+1 -> pair b[p+m] with w2[m].y
__device__ __forceinline__ void conv_row(ull* acc, const ull* a, const ull* b,
                                         const ulonglong2* __restrict__ wr2) {
#pragma unroll
    for (int m = 0; m < 8; ++m) {
        ulonglong2 w2 = wr2[m];          // LDS.128: taps 2m and 2m+1
#pragma unroll
        for (int p = 0; p < 8; ++p) acc[p] = fma2(a[p + m], w2.x, acc[p]);
        if (m < 7) {
#pragma unroll
            for (int p = 0; p < 8; ++p) acc[p] = fma2(b[p + m], w2.y, acc[p]);
        }
    }
}

// Load the 30-float window (15 aligned pairs) for input row ir; build 14 odd pairs.
__device__ __forceinline__ void load_win(const float* sA, int ir, int c0,
                                         ull* a, ull* b) {
    const unsigned xv = (((unsigned)ir) >> 1) & 7u;
    const char* rowp = reinterpret_cast<const char*>(sA) + ir * PITCH_B;
#pragma unroll
    for (int i = 0; i < 7; ++i) {
        ulonglong2 t = *reinterpret_cast<const ulonglong2*>(
            rowp + ((unsigned)((c0 + i) ^ xv) << 4));
        a[2 * i] = t.x;
        a[2 * i + 1] = t.y;
    }
    a[14] = *reinterpret_cast<const ull*>(rowp + ((unsigned)((c0 + 7) ^ xv) << 4));
#pragma unroll
    for (int q = 0; q < 14; ++q)
        b[q] = mkpair((unsigned)(a[q] >> 32), (unsigned)(a[q + 1] & 0xffffffffULL));
}

__global__ void __launch_bounds__(NTHR, 3)
conv15_kernel(const float* __restrict__ X, const float* __restrict__ Wt,
              const float* __restrict__ bias, float* __restrict__ out) {
    __shared__ float sA[IN_R * PITCH_F];
    __shared__ __align__(16) ull sW[15 * 16];   // row j at sW+16*j, taps 0..14 (+1 pad)

    const int tid = threadIdx.x;
    const int gro = blockIdx.y * TILE_R;
    const int gco = blockIdx.x * TILE_C;

    // Stage weights as duplicated f32x2 pairs into padded rows (16B-aligned pairs).
    for (int i = tid; i < 225; i += NTHR) {
        int row = i / 15;
        int t = i - row * 15;
        float w = Wt[i];
        unsigned wb = __float_as_uint(w);
        sW[row * 16 + t] = mkpair(wb, wb);
    }

    // Stage the input tile with 16B-granularity XOR swizzle: chunk ^ ((row>>1)&7).
    for (int idx = tid; idx < IN_R * LOAD_F4; idx += NTHR) {
        int r = idx / LOAD_F4;
        int c4 = idx - r * LOAD_F4;
        int gr = gro + r;
        int gc = gco + c4 * 4;
        float4 v = make_float4(0.f, 0.f, 0.f, 0.f);
        if (gr < IH && gc < IW)
            v = *reinterpret_cast<const float4*>(X + (size_t)gr * IW + gc);
        unsigned xv = (((unsigned)r) >> 1) & 7u;
        *reinterpret_cast<float4*>(sA + r * PITCH_F + (((unsigned)c4 ^ xv) << 2)) = v;
    }
    __syncthreads();

    const int warp = tid >> 5;         // 0..5 -> 16-col strip
    const int lane = tid & 31;
    const int c0 = warp * 4;           // window base in 16B chunks (floats warp*16)
    const int r0 = lane;               // one output row per lane

    ull acc[8];
#pragma unroll
    for (int p = 0; p < 8; ++p) acc[p] = 0ULL;

    ull a[15], b[14];

#pragma unroll 1
    for (int j = 0; j < 15; ++j) {
        load_win(sA, r0 + j, c0, a, b);
        conv_row(acc, a, b, reinterpret_cast<const ulonglong2*>(sW + j * 16));
    }

    // Epilogue: add bias, store as aligned 8B pairs (OW even -> pairs all-in/all-out).
    const unsigned bb = __float_as_uint(bias[0]);
    const ull bpair = mkpair(bb, bb);
    const int oc0 = gco + warp * 16;
    const int orow = gro + r0;
    if (orow < OH) {
        float* op = out + (size_t)orow * OW;
#pragma unroll
        for (int p = 0; p < 8; ++p) {
            int oc = oc0 + 2 * p;
            if (oc < OW)
                *reinterpret_cast<ull*>(op + oc) = add2(acc[p], bpair);
        }
    }
}

extern "C" void kernel_launch(void* const* d_in, const int* in_sizes, int n_in,
                              void* d_out, int out_size) {
    (void)in_sizes; (void)n_in; (void)out_size;
    const float* X = (const float*)d_in[0];
    const float* W = (const float*)d_in[1];
    const float* b = (const float*)d_in[2];
    float* out = (float*)d_out;

    dim3 grid((OW + TILE_C - 1) / TILE_C, (OH + TILE_R - 1) / TILE_R);
    conv15_kernel<<<grid, NTHR>>>(X, W, b, out);
}

// round 9
// speedup vs baseline: 1.1348x; 1.0616x over previous
#include <cuda_runtime.h>

#define IH 4096
#define IW 4096
#define OH 4082
#define OW 4082

#define TILE_R 64          // output rows per block (2 rows per lane)
#define TILE_C 96          // output cols per block (6 warps x 16)
#define NTHR   192
#define IN_R   78          // TILE_R + 14 input rows staged
#define PITCH_F 128        // smem row pitch in floats (32 x 16B chunks)
#define PITCH_B 512
#define LOAD_F4 28         // float4 per staged row (112 floats >= 110 needed)

typedef unsigned long long ull;

__device__ __forceinline__ ull fma2(ull a, ull b, ull c) {
    ull d;
    asm("fma.rn.f32x2 %0, %1, %2, %3;" : "=l"(d) : "l"(a), "l"(b), "l"(c));
    return d;
}
__device__ __forceinline__ ull add2(ull a, ull b) {
    ull d;
    asm("add.rn.f32x2 %0, %1, %2;" : "=l"(d) : "l"(a), "l"(b));
    return d;
}
__device__ __forceinline__ ull mkpair(unsigned lo, unsigned hi) {
    ull d;
    asm("mov.b64 %0, {%1, %2};" : "=l"(d) : "r"(lo), "r"(hi));
    return d;
}

// One weight row (15 taps, stored as 8 aligned ull-pairs) applied to 8 f32x2 accs.
// a[q] = (f[2q], f[2q+1])  q=0..14 ; b[q] = (f[2q+1], f[2q+2]) q=0..13
// kx=2m -> pair a[p+m] with w2[m].x ; kx=2m+1 -> pair b[p+m] with w2[m].y
__device__ __forceinline__ void conv_row(ull* acc, const ull* a, const ull* b,
                                         const ulonglong2* __restrict__ wr2) {
#pragma unroll
    for (int m = 0; m < 8; ++m) {
        ulonglong2 w2 = wr2[m];          // broadcast LDS.128: taps 2m, 2m+1
#pragma unroll
        for (int p = 0; p < 8; ++p) acc[p] = fma2(a[p + m], w2.x, acc[p]);
        if (m < 7) {
#pragma unroll
            for (int p = 0; p < 8; ++p) acc[p] = fma2(b[p + m], w2.y, acc[p]);
        }
    }
}

// Load the 30-float window (15 aligned pairs) for input row ir; build 14 odd pairs.
__device__ __forceinline__ void load_win(const float* sA, int ir, int c0,
                                         ull* a, ull* b) {
    const unsigned xv = (((unsigned)ir) >> 1) & 7u;
    const char* rowp = reinterpret_cast<const char*>(sA) + ir * PITCH_B;
#pragma unroll
    for (int i = 0; i < 7; ++i) {
        ulonglong2 t = *reinterpret_cast<const ulonglong2*>(
            rowp + ((unsigned)((c0 + i) ^ xv) << 4));
        a[2 * i] = t.x;
        a[2 * i + 1] = t.y;
    }
    a[14] = *reinterpret_cast<const ull*>(rowp + ((unsigned)((c0 + 7) ^ xv) << 4));
#pragma unroll
    for (int q = 0; q < 14; ++q)
        b[q] = mkpair((unsigned)(a[q] >> 32), (unsigned)(a[q + 1] & 0xffffffffULL));
}

__global__ void __launch_bounds__(NTHR, 3)
conv15_kernel(const float* __restrict__ X, const float* __restrict__ Wt,
              const float* __restrict__ bias, float* __restrict__ out) {
    __shared__ float sA[IN_R * PITCH_F];
    __shared__ __align__(16) ull sW[15 * 16];   // row j at sW+16*j, taps 0..14 (+pad)

    const int tid = threadIdx.x;
    const int gro = blockIdx.y * TILE_R;
    const int gco = blockIdx.x * TILE_C;

    // Stage weights as duplicated f32x2 pairs into padded rows (16B-aligned pairs).
    for (int i = tid; i < 225; i += NTHR) {
        int row = i / 15;
        int t = i - row * 15;
        float w = Wt[i];
        unsigned wb = __float_as_uint(w);
        sW[row * 16 + t] = mkpair(wb, wb);
    }

    // Stage the input tile with 16B-granularity XOR swizzle: chunk ^ ((row>>1)&7).
    for (int idx = tid; idx < IN_R * LOAD_F4; idx += NTHR) {
        int r = idx / LOAD_F4;
        int c4 = idx - r * LOAD_F4;
        int gr = gro + r;
        int gc = gco + c4 * 4;
        float4 v = make_float4(0.f, 0.f, 0.f, 0.f);
        if (gr < IH && gc < IW)
            v = *reinterpret_cast<const float4*>(X + (size_t)gr * IW + gc);
        unsigned xv = (((unsigned)r) >> 1) & 7u;
        *reinterpret_cast<float4*>(sA + r * PITCH_F + (((unsigned)c4 ^ xv) << 2)) = v;
    }
    __syncthreads();

    const int warp = tid >> 5;         // 0..5 -> 16-col strip
    const int lane = tid & 31;
    const int c0 = warp * 4;           // window base in 16B chunks (floats warp*16)
    const int r0 = lane * 2;           // two output rows per lane

    ull acc0[8], acc1[8];
#pragma unroll
    for (int p = 0; p < 8; ++p) { acc0[p] = 0ULL; acc1[p] = 0ULL; }

    ull a[15], b[14];

    // j = 0 : only row0 (ky = 0)
    load_win(sA, r0, c0, a, b);
    conv_row(acc0, a, b, reinterpret_cast<const ulonglong2*>(sW));

    // j = 1..14 : row0 (ky=j) and row1 (ky=j-1) share the same input row
#pragma unroll 1
    for (int j = 1; j <= 14; ++j) {
        load_win(sA, r0 + j, c0, a, b);
        conv_row(acc0, a, b, reinterpret_cast<const ulonglong2*>(sW + j * 16));
        conv_row(acc1, a, b, reinterpret_cast<const ulonglong2*>(sW + (j - 1) * 16));
    }

    // j = 15 : only row1 (ky = 14)
    load_win(sA, r0 + 15, c0, a, b);
    conv_row(acc1, a, b, reinterpret_cast<const ulonglong2*>(sW + 14 * 16));

    // Epilogue: add bias, store as aligned 8B pairs (OW even -> pairs all-in/all-out).
    const unsigned bb = __float_as_uint(bias[0]);
    const ull bpair = mkpair(bb, bb);
    const int oc0 = gco + warp * 16;

    {
        int orow = gro + r0;
        if (orow < OH) {
            float* op = out + (size_t)orow * OW;
#pragma unroll
            for (int p = 0; p < 8; ++p) {
                int oc = oc0 + 2 * p;
                if (oc < OW)
                    *reinterpret_cast<ull*>(op + oc) = add2(acc0[p], bpair);
            }
        }
    }
    {
        int orow = gro + r0 + 1;
        if (orow < OH) {
            float* op = out + (size_t)orow * OW;
#pragma unroll
            for (int p = 0; p < 8; ++p) {
                int oc = oc0 + 2 * p;
                if (oc < OW)
                    *reinterpret_cast<ull*>(op + oc) = add2(acc1[p], bpair);
            }
        }
    }
}

extern "C" void kernel_launch(void* const* d_in, const int* in_sizes, int n_in,
                              void* d_out, int out_size) {
    (void)in_sizes; (void)n_in; (void)out_size;
    const float* X = (const float*)d_in[0];
    const float* W = (const float*)d_in[1];
    const float* b = (const float*)d_in[2];
    float* out = (float*)d_out;

    // Allow 3 CTAs x 41.9 KB static smem per SM (B200: 228 KB unified L1/smem).
    // Host-side attribute set; deterministic and graph-capture-safe.
    static_assert(sizeof(float) == 4, "");
    cudaFuncSetAttribute(conv15_kernel,
                         cudaFuncAttributePreferredSharedMemoryCarveout,
                         cudaSharedmemCarveoutMaxShared);

    dim3 grid((OW + TILE_C - 1) / TILE_C, (OH + TILE_R - 1) / TILE_R);
    conv15_kernel<<<grid, NTHR>>>(X, W, b, out);
}